// round 2
// baseline (speedup 1.0000x reference)
#include <cuda_runtime.h>

#define D        64
#define K        1024
#define CT       256            // codes per smem tile
#define NTILES   (K / CT)       // 4
#define RPC      64             // rows per CTA
#define THREADS  256
#define XSTRIDE  65             // xd row stride in float2 units (pad: conflict-free LDS.64)

// smem layout (dynamic):
//   [0, 33280)          : xd   = float2 [RPC][XSTRIDE]  (x duplicated {v,v})
//   [33280, 98816)      : et   = float  [D][CT]         (code tile)
//   [98816, 99840)      : hs   = float  [CT]            (half-norm tile)
// reduction arrays alias the et region after the tile loop finishes.
#define SMEM_XD    0
#define SMEM_ET    33280
#define SMEM_HS    (33280 + 65536)
#define SMEM_TOTAL (SMEM_HS + 1024)

__device__ float g_hn[K];          // 0.5 * ||e_k||^2
__device__ float g_partials[4096]; // per-CTA sum of (q - x)^2

__device__ __forceinline__ unsigned long long fma2(unsigned long long a,
                                                   unsigned long long b,
                                                   unsigned long long c) {
    unsigned long long d;
    asm("fma.rn.f32x2 %0, %1, %2, %3;" : "=l"(d) : "l"(a), "l"(b), "l"(c));
    return d;
}

__device__ __forceinline__ float lo32(unsigned long long v) {
    return __uint_as_float((unsigned)(v & 0xffffffffULL));
}
__device__ __forceinline__ float hi32(unsigned long long v) {
    return __uint_as_float((unsigned)(v >> 32));
}

// ---------------------------------------------------------------------------
// Kernel 0: half squared norms of codebook columns. emb layout: [D][K].
// ---------------------------------------------------------------------------
__global__ void vq_norms(const float* __restrict__ emb) {
    int k = blockIdx.x * blockDim.x + threadIdx.x;
    if (k >= K) return;
    float s = 0.f;
#pragma unroll
    for (int d = 0; d < D; ++d) {
        float e = emb[(size_t)d * K + k];
        s = fmaf(e, e, s);
    }
    g_hn[k] = 0.5f * s;
}

// ---------------------------------------------------------------------------
// Kernel 1: main — per-row argmax(x.e - 0.5||e||^2), gather, partial MSE.
// Thread layout: rg = t & 15 (row group), cg = t >> 4 (code group).
// Thread tile: rows {rg, rg+16, rg+32, rg+48} x codes [cg*16, cg*16+16).
// ---------------------------------------------------------------------------
__global__ void __launch_bounds__(THREADS, 2)
vq_main(const float* __restrict__ x, const float* __restrict__ emb,
        float* __restrict__ out) {
    extern __shared__ char smem[];
    float2* xd = (float2*)(smem + SMEM_XD);
    float*  et = (float*) (smem + SMEM_ET);
    float*  hs = (float*) (smem + SMEM_HS);
    // aliases (used only after the tile loop):
    float*  sred = (float*)(smem + SMEM_ET);              // [64][16]
    int*    ired = (int*)  (smem + SMEM_ET + 4096);       // [64][16]
    int*    bidx = (int*)  (smem + SMEM_ET + 8192);       // [64]

    const int t  = threadIdx.x;
    const int rg = t & 15;
    const int cg = t >> 4;
    const int rowBase = blockIdx.x * RPC;

    // ---- load x rows into smem, duplicated as {v,v} --------------------
    const float4* xg = (const float4*)(x + (size_t)rowBase * D);
#pragma unroll
    for (int it = 0; it < 4; ++it) {
        int idx = it * THREADS + t;          // float4 index in [0, 64*16)
        int row = idx >> 4;
        int d0  = (idx & 15) << 2;
        float4 v = xg[idx];
        float2* p = &xd[row * XSTRIDE + d0];
        p[0] = make_float2(v.x, v.x);
        p[1] = make_float2(v.y, v.y);
        p[2] = make_float2(v.z, v.z);
        p[3] = make_float2(v.w, v.w);
    }

    float best_s[4];
    int   best_i[4];
#pragma unroll
    for (int i = 0; i < 4; ++i) { best_s[i] = -1e30f; best_i[i] = 0; }

    for (int tile = 0; tile < NTILES; ++tile) {
        const int cbase = tile * CT;
        __syncthreads();
        // load code tile [D][CT] (emb is [D][K]: fully coalesced float4)
#pragma unroll
        for (int it = 0; it < 16; ++it) {
            int idx = it * THREADS + t;      // float4 index in [0, 64*64)
            int d   = idx >> 6;              // / (CT/4)
            int c4  = (idx & 63) << 2;
            float4 v = *(const float4*)(emb + (size_t)d * K + cbase + c4);
            *(float4*)&et[d * CT + c4] = v;
        }
        hs[t] = g_hn[cbase + t];             // CT == THREADS
        __syncthreads();

        unsigned long long acc[4][8];
#pragma unroll
        for (int i = 0; i < 4; ++i)
#pragma unroll
            for (int j = 0; j < 8; ++j) acc[i][j] = 0ULL;

#pragma unroll 4
        for (int d = 0; d < D; ++d) {
            const float* ep = &et[d * CT + cg * 16];
            ulonglong2 qa = ((const ulonglong2*)ep)[0];
            ulonglong2 qb = ((const ulonglong2*)ep)[1];
            ulonglong2 qc = ((const ulonglong2*)ep)[2];
            ulonglong2 qd = ((const ulonglong2*)ep)[3];
            unsigned long long e2[8] = {qa.x, qa.y, qb.x, qb.y,
                                        qc.x, qc.y, qd.x, qd.y};
            unsigned long long xv[4];
#pragma unroll
            for (int i = 0; i < 4; ++i)
                xv[i] = *(const unsigned long long*)&xd[(rg + 16 * i) * XSTRIDE + d];
#pragma unroll
            for (int i = 0; i < 4; ++i)
#pragma unroll
                for (int j = 0; j < 8; ++j)
                    acc[i][j] = fma2(xv[i], e2[j], acc[i][j]);
        }

        // per-tile running argmax (codes visited in ascending order,
        // strict '>' keeps the lowest index on ties — matches jnp.argmin)
#pragma unroll
        for (int i = 0; i < 4; ++i) {
#pragma unroll
            for (int j = 0; j < 8; ++j) {
                int coff = cg * 16 + j * 2;
                float s0 = lo32(acc[i][j]) - hs[coff];
                float s1 = hi32(acc[i][j]) - hs[coff + 1];
                if (s0 > best_s[i]) { best_s[i] = s0; best_i[i] = cbase + coff; }
                if (s1 > best_s[i]) { best_s[i] = s1; best_i[i] = cbase + coff + 1; }
            }
        }
    }

    __syncthreads();   // done with et; reuse as reduction scratch
#pragma unroll
    for (int i = 0; i < 4; ++i) {
        int row = rg + 16 * i;
        sred[row * 16 + cg] = best_s[i];
        ired[row * 16 + cg] = best_i[i];
    }
    __syncthreads();
    if (t < 64) {
        float bs = sred[t * 16];
        int   bi = ired[t * 16];
#pragma unroll
        for (int c = 1; c < 16; ++c) {
            float s   = sred[t * 16 + c];
            int   idx = ired[t * 16 + c];
            if (s > bs || (s == bs && idx < bi)) { bs = s; bi = idx; }
        }
        bidx[t] = bi;
    }
    __syncthreads();

    // ---- gather quantized rows + partial MSE ----------------------------
    float lsum = 0.f;
#pragma unroll
    for (int it = 0; it < 16; ++it) {
        int elem = it * THREADS + t;     // in [0, 64*64)
        int row  = elem >> 6;
        int d    = elem & 63;
        int b    = bidx[row];
        float e  = emb[(size_t)d * K + b];    // codebook resident in L2
        float xv = xd[row * XSTRIDE + d].x;
        out[(size_t)(rowBase + row) * D + d] = e;
        float df = e - xv;
        lsum = fmaf(df, df, lsum);
    }

    // block reduce lsum (fixed order -> deterministic)
#pragma unroll
    for (int o = 16; o; o >>= 1) lsum += __shfl_down_sync(0xffffffffu, lsum, o);
    __shared__ float wsum[8];
    if ((t & 31) == 0) wsum[t >> 5] = lsum;
    __syncthreads();
    if (t == 0) {
        float s = 0.f;
#pragma unroll
        for (int w = 0; w < 8; ++w) s += wsum[w];
        g_partials[blockIdx.x] = s;
    }
}

// ---------------------------------------------------------------------------
// Kernel 2: deterministic final reduction -> loss = 1.25 * mean((q-x)^2)
// ---------------------------------------------------------------------------
__global__ void vq_finalize(float* __restrict__ out, int ncta,
                            float inv_total, int out_idx) {
    __shared__ float sh[256];
    int t = threadIdx.x;
    float s = 0.f;
    for (int i = t; i < ncta; i += 256) s += g_partials[i];
    sh[t] = s;
    __syncthreads();
    for (int o = 128; o; o >>= 1) {
        if (t < o) sh[t] += sh[t + o];
        __syncthreads();
    }
    if (t == 0) out[out_idx] = 1.25f * sh[0] * inv_total;
}

// ---------------------------------------------------------------------------
extern "C" void kernel_launch(void* const* d_in, const int* in_sizes, int n_in,
                              void* d_out, int out_size) {
    const float* x   = (const float*)d_in[0];   // [N, 64] flattened
    const float* emb = (const float*)d_in[1];   // [64, 1024]
    float* out = (float*)d_out;                 // [N*64 quantized ..., loss]

    int nelem = in_sizes[0];         // N * D
    int nrows = nelem / D;           // 65536
    int ncta  = nrows / RPC;         // 1024

    cudaFuncSetAttribute(vq_main, cudaFuncAttributeMaxDynamicSharedMemorySize,
                         SMEM_TOTAL);

    vq_norms<<<(K + 255) / 256, 256>>>(emb);
    vq_main<<<ncta, THREADS, SMEM_TOTAL>>>(x, emb, out);
    vq_finalize<<<1, 256>>>(out, ncta, 1.0f / (float)nelem, out_size - 1);
}

// round 6
// speedup vs baseline: 2.2338x; 2.2338x over previous
#include <cuda_runtime.h>
#include <cuda_fp16.h>
#include <cstdint>

#define D        64
#define K        1024
#define KEFF     192           // [xh | xh | xl] . [eh | el | eh]
#define M_TILE   128           // rows per CTA
#define NCHK     64            // codes per chunk
#define NCHUNK   (K / NCHK)    // 16
#define THREADS  256
#define KS       200           // smem K stride in halves (400 B, conflict-free)

// ---- dynamic smem layout (bytes) ----
#define XS_OFF   0                      // 128 x KS halves  (51200)
#define ES_OFF   51200                  // 64 x KS halves   (25600)
#define HN_OFF   76800                  // float[1024]      (4096)
#define BIDX_OFF 80896                  // int[128]
#define WSUM_OFF 81408                  // float[8]
#define SM_TOTAL 81440

__device__ float g_hn[K];                          // 0.5*||e_k||^2
__device__ float g_ebt[K * D];                     // [K][D] fp32 (gather)
__device__ __align__(16) __half g_ehl[K * KEFF];   // [K][eh|el|eh] fp16
__device__ float g_partials[1024];

__device__ __forceinline__ uint32_t pack2(__half lo, __half hi) {
    return (uint32_t)__half_as_ushort(lo) |
           ((uint32_t)__half_as_ushort(hi) << 16);
}

// ---------------------------------------------------------------------------
__global__ void vq_norms(const float* __restrict__ emb) {
    int k = blockIdx.x * blockDim.x + threadIdx.x;
    if (k >= K) return;
    float s = 0.f;
#pragma unroll
    for (int d = 0; d < D; ++d) {
        float e = emb[(size_t)d * K + k];
        s = fmaf(e, e, s);
    }
    g_hn[k] = 0.5f * s;
}

__global__ void vq_prep(const float* __restrict__ emb) {
    int i = blockIdx.x * blockDim.x + threadIdx.x;   // over K*D
    int k = i >> 6, d = i & 63;
    float e = emb[(size_t)d * K + k];
    g_ebt[i] = e;
    __half eh = __float2half_rn(e);
    __half el = __float2half_rn(e - __half2float(eh));
    g_ehl[k * KEFF + d]       = eh;
    g_ehl[k * KEFF + 64 + d]  = el;
    g_ehl[k * KEFF + 128 + d] = eh;
}

// ---------------------------------------------------------------------------
__device__ __forceinline__ void mma16816(float& c0, float& c1, float& c2,
                                         float& c3, uint32_t a0, uint32_t a1,
                                         uint32_t a2, uint32_t a3,
                                         uint32_t b0, uint32_t b1) {
    asm volatile(
        "mma.sync.aligned.m16n8k16.row.col.f32.f16.f16.f32 "
        "{%0,%1,%2,%3}, {%4,%5,%6,%7}, {%8,%9}, {%0,%1,%2,%3};"
        : "+f"(c0), "+f"(c1), "+f"(c2), "+f"(c3)
        : "r"(a0), "r"(a1), "r"(a2), "r"(a3), "r"(b0), "r"(b1));
}

__global__ void __launch_bounds__(THREADS)
vq_main(const float* __restrict__ x, float* __restrict__ out) {
    extern __shared__ char smem[];
    char*  xs   = smem + XS_OFF;
    char*  es   = smem + ES_OFF;
    float* hn   = (float*)(smem + HN_OFF);
    int*   bidx = (int*)  (smem + BIDX_OFF);
    float* wsum = (float*)(smem + WSUM_OFF);

    const int t    = threadIdx.x;
    const int w    = t >> 5;
    const int lane = t & 31;
    const int n4   = lane >> 2;       // 0..7  (row-in-tile / code-in-tile)
    const int q    = lane & 3;        // 0..3  (k / column quad)
    const int rowBase = blockIdx.x * M_TILE;

    // ---- half norms ----
#pragma unroll
    for (int i = 0; i < 4; ++i) hn[i * THREADS + t] = g_hn[i * THREADS + t];

    // ---- stage x tile: split fp32 -> [xh | xh | xl] fp16, stride KS ----
    const float4* xg = (const float4*)(x + (size_t)rowBase * D);
#pragma unroll
    for (int it = 0; it < 8; ++it) {
        int u = it * THREADS + t;           // float4 idx in [0, 2048)
        int r = u >> 4, d = (u & 15) << 2;
        float4 v = xg[u];
        __half h0 = __float2half_rn(v.x), h1 = __float2half_rn(v.y);
        __half h2 = __float2half_rn(v.z), h3 = __float2half_rn(v.w);
        __half l0 = __float2half_rn(v.x - __half2float(h0));
        __half l1 = __float2half_rn(v.y - __half2float(h1));
        __half l2 = __float2half_rn(v.z - __half2float(h2));
        __half l3 = __float2half_rn(v.w - __half2float(h3));
        uint2 hv, lv;
        hv.x = pack2(h0, h1);
        hv.y = pack2(h2, h3);
        lv.x = pack2(l0, l1);
        lv.y = pack2(l2, l3);
        char* base = xs + r * (KS * 2) + d * 2;
        *(uint2*)(base)       = hv;          // seg0: xh
        *(uint2*)(base + 128) = hv;          // seg1: xh
        *(uint2*)(base + 256) = lv;          // seg2: xl
    }

    // ---- stage B chunk 0 into regs ----
    const uint4* gB = (const uint4*)g_ehl;   // 24 uint4 per code
    uint4 st[6];
#pragma unroll
    for (int j = 0; j < 6; ++j) st[j] = gB[j * THREADS + t];

    __syncthreads();                          // xs ready

    // ---- preload A fragments (persistent across all chunks) ----
    uint32_t afr[12][4];
    {
        const char* ab = xs + (w * 16 + n4) * (KS * 2) + q * 4;
#pragma unroll
        for (int s = 0; s < 12; ++s) {
            afr[s][0] = *(const uint32_t*)(ab + 32 * s);
            afr[s][1] = *(const uint32_t*)(ab + 32 * s + 8 * (KS * 2));
            afr[s][2] = *(const uint32_t*)(ab + 32 * s + 16);
            afr[s][3] = *(const uint32_t*)(ab + 32 * s + 8 * (KS * 2) + 16);
        }
    }

    // write staged chunk 0 to smem
#pragma unroll
    for (int j = 0; j < 6; ++j) {
        int u = j * THREADS + t;
        int code = u / 24, cell = u % 24;
        *(uint4*)(es + code * (KS * 2) + cell * 16) = st[j];
    }
    __syncthreads();

    float bs0 = -1e30f, bs1 = -1e30f;
    int   bi0 = 0,      bi1 = 0;

    for (int c = 0; c < NCHUNK; ++c) {
        // prefetch next chunk to regs (overlaps with mma)
        if (c + 1 < NCHUNK) {
            const uint4* gc = gB + (size_t)(c + 1) * (NCHK * 24);
#pragma unroll
            for (int j = 0; j < 6; ++j) st[j] = gc[j * THREADS + t];
        }

        // ---- compute chunk c: 8 ntiles x 12 ksteps ----
        float acc[8][4];
#pragma unroll
        for (int nt = 0; nt < 8; ++nt)
#pragma unroll
            for (int i = 0; i < 4; ++i) acc[nt][i] = 0.f;

        const char* bb = es + n4 * (KS * 2) + q * 4;
#pragma unroll
        for (int s = 0; s < 12; ++s) {
#pragma unroll
            for (int nt = 0; nt < 8; ++nt) {
                uint32_t b0 = *(const uint32_t*)(bb + nt * (8 * KS * 2) + 32 * s);
                uint32_t b1 = *(const uint32_t*)(bb + nt * (8 * KS * 2) + 32 * s + 16);
                mma16816(acc[nt][0], acc[nt][1], acc[nt][2], acc[nt][3],
                         afr[s][0], afr[s][1], afr[s][2], afr[s][3], b0, b1);
            }
        }

        // ---- epilogue: score = acc - hn, running argmax ----
#pragma unroll
        for (int nt = 0; nt < 8; ++nt) {
            int cb = c * NCHK + nt * 8 + q * 2;
            float2 h = *(const float2*)&hn[cb];
            float s0 = acc[nt][0] - h.x;
            float s1 = acc[nt][1] - h.y;
            float s2 = acc[nt][2] - h.x;
            float s3 = acc[nt][3] - h.y;
            if (s0 > bs0) { bs0 = s0; bi0 = cb; }
            if (s1 > bs0) { bs0 = s1; bi0 = cb + 1; }
            if (s2 > bs1) { bs1 = s2; bi1 = cb; }
            if (s3 > bs1) { bs1 = s3; bi1 = cb + 1; }
        }

        __syncthreads();                      // everyone done reading es
        if (c + 1 < NCHUNK) {
#pragma unroll
            for (int j = 0; j < 6; ++j) {
                int u = j * THREADS + t;
                int code = u / 24, cell = u % 24;
                *(uint4*)(es + code * (KS * 2) + cell * 16) = st[j];
            }
        }
        __syncthreads();
    }

    // ---- reduce (score, idx) across the 4 lanes sharing each row ----
#pragma unroll
    for (int off = 1; off <= 2; off <<= 1) {
        float os0 = __shfl_xor_sync(0xffffffffu, bs0, off);
        int   oi0 = __shfl_xor_sync(0xffffffffu, bi0, off);
        float os1 = __shfl_xor_sync(0xffffffffu, bs1, off);
        int   oi1 = __shfl_xor_sync(0xffffffffu, bi1, off);
        if (os0 > bs0 || (os0 == bs0 && oi0 < bi0)) { bs0 = os0; bi0 = oi0; }
        if (os1 > bs1 || (os1 == bs1 && oi1 < bi1)) { bs1 = os1; bi1 = oi1; }
    }
    if (q == 0) {
        bidx[w * 16 + n4]     = bi0;
        bidx[w * 16 + n4 + 8] = bi1;
    }
    __syncthreads();

    // ---- gather quantized rows + partial MSE ----
    float lsum = 0.f;
    const float* xf = x + (size_t)rowBase * D;
    float* of = out + (size_t)rowBase * D;
#pragma unroll
    for (int it = 0; it < 32; ++it) {
        int e = it * THREADS + t;
        int r = e >> 6, d = e & 63;
        int b = bidx[r];
        float qv = g_ebt[b * D + d];
        float xv = xf[e];
        of[e] = qv;
        float df = qv - xv;
        lsum = fmaf(df, df, lsum);
    }
#pragma unroll
    for (int o = 16; o; o >>= 1) lsum += __shfl_down_sync(0xffffffffu, lsum, o);
    if (lane == 0) wsum[w] = lsum;
    __syncthreads();
    if (t == 0) {
        float s = 0.f;
#pragma unroll
        for (int i = 0; i < 8; ++i) s += wsum[i];
        g_partials[blockIdx.x] = s;
    }
}

// ---------------------------------------------------------------------------
__global__ void vq_finalize(float* __restrict__ out, int ncta,
                            float inv_total, int out_idx) {
    __shared__ float sh[256];
    int t = threadIdx.x;
    float s = 0.f;
    for (int i = t; i < ncta; i += 256) s += g_partials[i];
    sh[t] = s;
    __syncthreads();
    for (int o = 128; o; o >>= 1) {
        if (t < o) sh[t] += sh[t + o];
        __syncthreads();
    }
    if (t == 0) out[out_idx] = 1.25f * sh[0] * inv_total;
}

// ---------------------------------------------------------------------------
extern "C" void kernel_launch(void* const* d_in, const int* in_sizes, int n_in,
                              void* d_out, int out_size) {
    const float* x   = (const float*)d_in[0];   // [N, 64]
    const float* emb = (const float*)d_in[1];   // [64, 1024]
    float* out = (float*)d_out;

    int nelem = in_sizes[0];
    int nrows = nelem / D;
    int ncta  = nrows / M_TILE;                 // 512

    cudaFuncSetAttribute(vq_main, cudaFuncAttributeMaxDynamicSharedMemorySize,
                         SM_TOTAL);

    vq_norms<<<(K + 255) / 256, 256>>>(emb);
    vq_prep<<<(K * D) / 256, 256>>>(emb);
    vq_main<<<ncta, THREADS, SM_TOTAL>>>(x, out);
    vq_finalize<<<1, 256>>>(out, ncta, 1.0f / (float)nelem, out_size - 1);
}

// round 7
// speedup vs baseline: 2.2734x; 1.0177x over previous
#include <cuda_runtime.h>
#include <cuda_fp16.h>
#include <cstdint>

#define D        64
#define K        1024
#define KEFF     192           // [xh | xh | xl] . [eh | el | eh]
#define M_TILE   128           // rows per CTA
#define NCHK     64            // codes per chunk
#define NCHUNK   (K / NCHK)    // 16
#define THREADS  256
#define KS       200           // xs stride in halves (conflict-free A loads)

// uint4-per-thread count for one chunk of fragment-order B
#define CHUNK_U4 1536          // 64 codes * 192 halves * 2B / 16B

// ---- dynamic smem layout (bytes) ----
#define XS_OFF   0                      // 128 x KS halves  (51200)
#define ES_OFF   51200                  // fragment-order chunk (24576)
#define HN_OFF   75776                  // float[1024]
#define BIDX_OFF 79872                  // int[128]
#define WSUM_OFF 80384                  // float[8]
#define FLAG_OFF 80416                  // int[1]
#define SM_TOTAL 80448

__device__ float g_hn[K];                            // 0.5*||e_k||^2
__device__ float g_ebt[K * D];                       // [K][D] fp32 (gather)
__device__ __align__(16) uint32_t g_bfrag[K * KEFF / 2]; // fragment-order B
__device__ float g_partials[1024];
__device__ unsigned g_ticket = 0;

__device__ __forceinline__ uint32_t pack2(__half lo, __half hi) {
    return (uint32_t)__half_as_ushort(lo) |
           ((uint32_t)__half_as_ushort(hi) << 16);
}

// ---------------------------------------------------------------------------
// prep: blocks [0,96)  -> fragment-order B  (24576 uint4)
//       blocks [96,160)-> transpose g_ebt + half-norms g_hn
// fragment mapping for mma.m16n8k16.row.col:
//   lane: q = lane&3, n4 = lane>>2; code = c*64 + nt*8 + n4
//   s-step s: kk = 16s + 2q; b0 = {v(kk), v(kk+1)}, b1 = {v(kk+8), v(kk+9)}
//   v(j): seg = j>>6 (0:eh, 1:el, 2:eh), d = j&63   (segments never straddle)
// ---------------------------------------------------------------------------
__global__ void vq_prep(const float* __restrict__ emb) {
    const int b = blockIdx.x, t = threadIdx.x;
    if (b < 96) {
        int idx  = b * 256 + t;            // [0, 24576)
        int c    = idx / CHUNK_U4;
        int r    = idx - c * CHUNK_U4;
        int s2   = r >> 8;                 // 0..5
        int nt   = (r >> 5) & 7;
        int lane = r & 31;
        int q = lane & 3, n4 = lane >> 2;
        int code = c * 64 + nt * 8 + n4;
        uint32_t v[4];
#pragma unroll
        for (int h = 0; h < 2; ++h) {
            int s  = 2 * s2 + h;
            int kk = 16 * s + 2 * q;
            int seg = kk >> 6;
            int d0  = kk & 63;
            float e0 = emb[(size_t)(d0    ) * K + code];
            float e1 = emb[(size_t)(d0 + 1) * K + code];
            float e2 = emb[(size_t)(d0 + 8) * K + code];
            float e3 = emb[(size_t)(d0 + 9) * K + code];
            __half h0 = __float2half_rn(e0), h1 = __float2half_rn(e1);
            __half h2 = __float2half_rn(e2), h3 = __float2half_rn(e3);
            if (seg == 1) {
                h0 = __float2half_rn(e0 - __half2float(h0));
                h1 = __float2half_rn(e1 - __half2float(h1));
                h2 = __float2half_rn(e2 - __half2float(h2));
                h3 = __float2half_rn(e3 - __half2float(h3));
            }
            v[2 * h + 0] = pack2(h0, h1);
            v[2 * h + 1] = pack2(h2, h3);
        }
        ((uint4*)g_bfrag)[idx] = make_uint4(v[0], v[1], v[2], v[3]);
    } else {
        int i  = (b - 96) * 256 + t;       // [0, 16384)
        int k  = i >> 4;
        int d4 = (i & 15) << 2;
        float v0 = emb[(size_t)(d4 + 0) * K + k];
        float v1 = emb[(size_t)(d4 + 1) * K + k];
        float v2 = emb[(size_t)(d4 + 2) * K + k];
        float v3 = emb[(size_t)(d4 + 3) * K + k];
        *(float4*)&g_ebt[k * D + d4] = make_float4(v0, v1, v2, v3);
        float ps = v0 * v0 + v1 * v1 + v2 * v2 + v3 * v3;
#pragma unroll
        for (int o = 8; o; o >>= 1)
            ps += __shfl_down_sync(0xffffffffu, ps, o, 16);
        if ((t & 15) == 0) g_hn[k] = 0.5f * ps;
    }
}

// ---------------------------------------------------------------------------
__device__ __forceinline__ void mma16816(float& c0, float& c1, float& c2,
                                         float& c3, uint32_t a0, uint32_t a1,
                                         uint32_t a2, uint32_t a3,
                                         uint32_t b0, uint32_t b1) {
    asm volatile(
        "mma.sync.aligned.m16n8k16.row.col.f32.f16.f16.f32 "
        "{%0,%1,%2,%3}, {%4,%5,%6,%7}, {%8,%9}, {%0,%1,%2,%3};"
        : "+f"(c0), "+f"(c1), "+f"(c2), "+f"(c3)
        : "r"(a0), "r"(a1), "r"(a2), "r"(a3), "r"(b0), "r"(b1));
}

__global__ void __launch_bounds__(THREADS)
vq_main(const float* __restrict__ x, float* __restrict__ out,
        float inv_total, int out_idx) {
    extern __shared__ char smem[];
    char*  xs   = smem + XS_OFF;
    char*  es   = smem + ES_OFF;
    float* hn   = (float*)(smem + HN_OFF);
    int*   bidx = (int*)  (smem + BIDX_OFF);
    float* wsum = (float*)(smem + WSUM_OFF);
    int*   flag = (int*)  (smem + FLAG_OFF);

    const int t    = threadIdx.x;
    const int w    = t >> 5;
    const int lane = t & 31;
    const int n4   = lane >> 2;
    const int q    = lane & 3;
    const int rowBase = blockIdx.x * M_TILE;

    // ---- half norms ----
#pragma unroll
    for (int i = 0; i < 4; ++i) hn[i * THREADS + t] = g_hn[i * THREADS + t];

    // ---- stage x tile: split fp32 -> [xh | xh | xl] fp16, stride KS ----
    const float4* xg = (const float4*)(x + (size_t)rowBase * D);
#pragma unroll
    for (int it = 0; it < 8; ++it) {
        int u = it * THREADS + t;
        int r = u >> 4, d = (u & 15) << 2;
        float4 v = xg[u];
        __half h0 = __float2half_rn(v.x), h1 = __float2half_rn(v.y);
        __half h2 = __float2half_rn(v.z), h3 = __float2half_rn(v.w);
        __half l0 = __float2half_rn(v.x - __half2float(h0));
        __half l1 = __float2half_rn(v.y - __half2float(h1));
        __half l2 = __float2half_rn(v.z - __half2float(h2));
        __half l3 = __float2half_rn(v.w - __half2float(h3));
        uint2 hv, lv;
        hv.x = pack2(h0, h1);
        hv.y = pack2(h2, h3);
        lv.x = pack2(l0, l1);
        lv.y = pack2(l2, l3);
        char* base = xs + r * (KS * 2) + d * 2;
        *(uint2*)(base)       = hv;
        *(uint2*)(base + 128) = hv;
        *(uint2*)(base + 256) = lv;
    }

    // ---- stage B chunk 0 into regs ----
    const uint4* gB = (const uint4*)g_bfrag;
    uint4 st[6];
#pragma unroll
    for (int j = 0; j < 6; ++j) st[j] = gB[j * THREADS + t];

    __syncthreads();

    // ---- preload A fragments (persistent across all chunks) ----
    uint32_t afr[12][4];
    {
        const char* ab = xs + (w * 16 + n4) * (KS * 2) + q * 4;
#pragma unroll
        for (int s = 0; s < 12; ++s) {
            afr[s][0] = *(const uint32_t*)(ab + 32 * s);
            afr[s][1] = *(const uint32_t*)(ab + 32 * s + 8 * (KS * 2));
            afr[s][2] = *(const uint32_t*)(ab + 32 * s + 16);
            afr[s][3] = *(const uint32_t*)(ab + 32 * s + 8 * (KS * 2) + 16);
        }
    }

    // write staged chunk 0 to smem (identity copy, fragment order)
#pragma unroll
    for (int j = 0; j < 6; ++j)
        *(uint4*)(es + (j * THREADS + t) * 16) = st[j];
    __syncthreads();

    float bs0 = -1e30f, bs1 = -1e30f;
    int   bi0 = 0,      bi1 = 0;

    for (int c = 0; c < NCHUNK; ++c) {
        if (c + 1 < NCHUNK) {
            const uint4* gc = gB + (size_t)(c + 1) * CHUNK_U4;
#pragma unroll
            for (int j = 0; j < 6; ++j) st[j] = gc[j * THREADS + t];
        }

        float acc[8][4];
#pragma unroll
        for (int nt = 0; nt < 8; ++nt)
#pragma unroll
            for (int i = 0; i < 4; ++i) acc[nt][i] = 0.f;

#pragma unroll
        for (int s2 = 0; s2 < 6; ++s2) {
#pragma unroll
            for (int nt = 0; nt < 8; ++nt) {
                uint4 bv = *(const uint4*)(es +
                    (((s2 * 8 + nt) * 32) + lane) * 16);
                mma16816(acc[nt][0], acc[nt][1], acc[nt][2], acc[nt][3],
                         afr[2 * s2][0], afr[2 * s2][1],
                         afr[2 * s2][2], afr[2 * s2][3], bv.x, bv.y);
                mma16816(acc[nt][0], acc[nt][1], acc[nt][2], acc[nt][3],
                         afr[2 * s2 + 1][0], afr[2 * s2 + 1][1],
                         afr[2 * s2 + 1][2], afr[2 * s2 + 1][3], bv.z, bv.w);
            }
        }

        // ---- epilogue: score = acc - hn, running argmax ----
#pragma unroll
        for (int nt = 0; nt < 8; ++nt) {
            int cb = c * NCHK + nt * 8 + q * 2;
            float2 h = *(const float2*)&hn[cb];
            float s0 = acc[nt][0] - h.x;
            float s1 = acc[nt][1] - h.y;
            float s2v = acc[nt][2] - h.x;
            float s3 = acc[nt][3] - h.y;
            if (s0 > bs0) { bs0 = s0; bi0 = cb; }
            if (s1 > bs0) { bs0 = s1; bi0 = cb + 1; }
            if (s2v > bs1) { bs1 = s2v; bi1 = cb; }
            if (s3 > bs1) { bs1 = s3; bi1 = cb + 1; }
        }

        __syncthreads();
        if (c + 1 < NCHUNK) {
#pragma unroll
            for (int j = 0; j < 6; ++j)
                *(uint4*)(es + (j * THREADS + t) * 16) = st[j];
        }
        __syncthreads();
    }

    // ---- reduce (score, idx) across the 4 lanes sharing each row ----
#pragma unroll
    for (int off = 1; off <= 2; off <<= 1) {
        float os0 = __shfl_xor_sync(0xffffffffu, bs0, off);
        int   oi0 = __shfl_xor_sync(0xffffffffu, bi0, off);
        float os1 = __shfl_xor_sync(0xffffffffu, bs1, off);
        int   oi1 = __shfl_xor_sync(0xffffffffu, bi1, off);
        if (os0 > bs0 || (os0 == bs0 && oi0 < bi0)) { bs0 = os0; bi0 = oi0; }
        if (os1 > bs1 || (os1 == bs1 && oi1 < bi1)) { bs1 = os1; bi1 = oi1; }
    }
    if (q == 0) {
        bidx[w * 16 + n4]     = bi0;
        bidx[w * 16 + n4 + 8] = bi1;
    }
    __syncthreads();

    // ---- gather quantized rows + partial MSE ----
    float lsum = 0.f;
    const float* xf = x + (size_t)rowBase * D;
    float* of = out + (size_t)rowBase * D;
#pragma unroll
    for (int it = 0; it < 32; ++it) {
        int e = it * THREADS + t;
        int r = e >> 6, d = e & 63;
        int b = bidx[r];
        float qv = g_ebt[b * D + d];
        float xv = xf[e];
        of[e] = qv;
        float df = qv - xv;
        lsum = fmaf(df, df, lsum);
    }
#pragma unroll
    for (int o = 16; o; o >>= 1) lsum += __shfl_down_sync(0xffffffffu, lsum, o);
    if (lane == 0) wsum[w] = lsum;
    __syncthreads();

    // ---- last-CTA loss finalization (deterministic fixed-order sum) ----
    if (t == 0) {
        float s = 0.f;
#pragma unroll
        for (int i = 0; i < 8; ++i) s += wsum[i];
        g_partials[blockIdx.x] = s;
        __threadfence();
        unsigned tk = atomicAdd(&g_ticket, 1u);
        flag[0] = (tk == gridDim.x - 1) ? 1 : 0;
    }
    __syncthreads();
    if (flag[0]) {
        const int ncta = gridDim.x;
        volatile const float* gp = g_partials;
        float s = 0.f;
        for (int i = t; i < ncta; i += THREADS) s += gp[i];
#pragma unroll
        for (int o = 16; o; o >>= 1)
            s += __shfl_down_sync(0xffffffffu, s, o);
        if (lane == 0) wsum[w] = s;
        __syncthreads();
        if (t == 0) {
            float tot = 0.f;
#pragma unroll
            for (int i = 0; i < 8; ++i) tot += wsum[i];
            out[out_idx] = 1.25f * tot * inv_total;
            g_ticket = 0;                  // reset for graph replay
        }
    }
}

// ---------------------------------------------------------------------------
extern "C" void kernel_launch(void* const* d_in, const int* in_sizes, int n_in,
                              void* d_out, int out_size) {
    const float* x   = (const float*)d_in[0];   // [N, 64]
    const float* emb = (const float*)d_in[1];   // [64, 1024]
    float* out = (float*)d_out;

    int nelem = in_sizes[0];
    int nrows = nelem / D;
    int ncta  = nrows / M_TILE;                 // 512

    cudaFuncSetAttribute(vq_main, cudaFuncAttributeMaxDynamicSharedMemorySize,
                         SM_TOTAL);

    vq_prep<<<160, 256>>>(emb);
    vq_main<<<ncta, THREADS, SM_TOTAL>>>(x, out, 1.0f / (float)nelem,
                                         out_size - 1);
}

// round 11
// speedup vs baseline: 2.6578x; 1.1691x over previous
#include <cuda_runtime.h>
#include <cuda_fp16.h>
#include <cstdint>

#define D        64
#define K        1024
#define KEFF     192           // [xh | xh | xl] . [eh | el | eh]
#define M_TILE   128           // rows per CTA
#define NCHK     64            // codes per chunk
#define NCHUNK   (K / NCHK)    // 16
#define THREADS  128           // 4 warps, M=32 rows per warp
#define KS       200           // xs stride in halves (conflict-free A loads)

#define CHUNK_U4 1536          // uint4 per fragment-order chunk (24576 B)

// ---- dynamic smem layout (bytes) ----
#define ES0_OFF  0                      // chunk buffer 0 (24576)
#define ES1_OFF  24576                  // chunk buffer 1 (24576)
#define XS_OFF   49152                  // 128 x KS halves (51200)
#define HN_OFF   100352                 // float[1024]
#define BIDX_OFF 104448                 // int[128]
#define WSUM_OFF 104960                 // float[4]
#define FLAG_OFF 104976                 // int[1]
#define SM_TOTAL 104992

__device__ float g_hn[K];                            // 0.5*||e_k||^2
__device__ float g_ebt[K * D];                       // [K][D] fp32 (gather)
__device__ __align__(16) uint32_t g_bfrag[K * KEFF / 2]; // fragment-order B
__device__ float g_partials[1024];
__device__ unsigned g_ticket = 0;

__device__ __forceinline__ uint32_t pack2(__half lo, __half hi) {
    return (uint32_t)__half_as_ushort(lo) |
           ((uint32_t)__half_as_ushort(hi) << 16);
}
__device__ __forceinline__ uint32_t smem_u32(const void* p) {
    uint32_t a;
    asm("{ .reg .u64 t; cvta.to.shared.u64 t, %1; cvt.u32.u64 %0, t; }"
        : "=r"(a) : "l"(p));
    return a;
}
__device__ __forceinline__ void cp16(uint32_t dst, const void* src) {
    asm volatile("cp.async.cg.shared.global [%0], [%1], 16;"
                 :: "r"(dst), "l"(src));
}
#define CP_COMMIT() asm volatile("cp.async.commit_group;" ::: "memory")
#define CP_WAIT0()  asm volatile("cp.async.wait_group 0;" ::: "memory")

// ---------------------------------------------------------------------------
// prep: blocks [0,96)  -> fragment-order B  (24576 uint4)
//       blocks [96,160)-> transpose g_ebt + half-norms g_hn
// ---------------------------------------------------------------------------
__global__ void vq_prep(const float* __restrict__ emb) {
    const int b = blockIdx.x, t = threadIdx.x;
    if (b < 96) {
        int idx  = b * 256 + t;            // [0, 24576)
        int c    = idx / CHUNK_U4;
        int r    = idx - c * CHUNK_U4;
        int s2   = r >> 8;                 // 0..5
        int nt   = (r >> 5) & 7;
        int lane = r & 31;
        int q = lane & 3, n4 = lane >> 2;
        int code = c * 64 + nt * 8 + n4;
        uint32_t v[4];
#pragma unroll
        for (int h = 0; h < 2; ++h) {
            int s  = 2 * s2 + h;
            int kk = 16 * s + 2 * q;
            int seg = kk >> 6;
            int d0  = kk & 63;
            float e0 = emb[(size_t)(d0    ) * K + code];
            float e1 = emb[(size_t)(d0 + 1) * K + code];
            float e2 = emb[(size_t)(d0 + 8) * K + code];
            float e3 = emb[(size_t)(d0 + 9) * K + code];
            __half h0 = __float2half_rn(e0), h1 = __float2half_rn(e1);
            __half h2 = __float2half_rn(e2), h3 = __float2half_rn(e3);
            if (seg == 1) {
                h0 = __float2half_rn(e0 - __half2float(h0));
                h1 = __float2half_rn(e1 - __half2float(h1));
                h2 = __float2half_rn(e2 - __half2float(h2));
                h3 = __float2half_rn(e3 - __half2float(h3));
            }
            v[2 * h + 0] = pack2(h0, h1);
            v[2 * h + 1] = pack2(h2, h3);
        }
        ((uint4*)g_bfrag)[idx] = make_uint4(v[0], v[1], v[2], v[3]);
    } else {
        int i  = (b - 96) * 256 + t;       // [0, 16384)
        int k  = i >> 4;
        int d4 = (i & 15) << 2;
        float v0 = emb[(size_t)(d4 + 0) * K + k];
        float v1 = emb[(size_t)(d4 + 1) * K + k];
        float v2 = emb[(size_t)(d4 + 2) * K + k];
        float v3 = emb[(size_t)(d4 + 3) * K + k];
        *(float4*)&g_ebt[k * D + d4] = make_float4(v0, v1, v2, v3);
        float ps = v0 * v0 + v1 * v1 + v2 * v2 + v3 * v3;
#pragma unroll
        for (int o = 8; o; o >>= 1)
            ps += __shfl_down_sync(0xffffffffu, ps, o, 16);
        if ((t & 15) == 0) g_hn[k] = 0.5f * ps;
    }
}

// ---------------------------------------------------------------------------
__device__ __forceinline__ void mma16816(float& c0, float& c1, float& c2,
                                         float& c3, uint32_t a0, uint32_t a1,
                                         uint32_t a2, uint32_t a3,
                                         uint32_t b0, uint32_t b1) {
    asm volatile(
        "mma.sync.aligned.m16n8k16.row.col.f32.f16.f16.f32 "
        "{%0,%1,%2,%3}, {%4,%5,%6,%7}, {%8,%9}, {%0,%1,%2,%3};"
        : "+f"(c0), "+f"(c1), "+f"(c2), "+f"(c3)
        : "r"(a0), "r"(a1), "r"(a2), "r"(a3), "r"(b0), "r"(b1));
}

__global__ void __launch_bounds__(THREADS, 2)
vq_main(const float* __restrict__ x, float* __restrict__ out,
        float inv_total, int out_idx) {
    extern __shared__ char smem[];
    char*  xs   = smem + XS_OFF;
    float* hn   = (float*)(smem + HN_OFF);
    int*   bidx = (int*)  (smem + BIDX_OFF);
    float* wsum = (float*)(smem + WSUM_OFF);
    int*   flag = (int*)  (smem + FLAG_OFF);
    const uint32_t sb = smem_u32(smem);

    const int t    = threadIdx.x;
    const int w    = t >> 5;
    const int lane = t & 31;
    const int n4   = lane >> 2;
    const int q    = lane & 3;
    const int rowBase = blockIdx.x * M_TILE;

    // ---- prefetch chunk 0 via cp.async (overlaps A staging) ----
    const uint4* gB = (const uint4*)g_bfrag;
#pragma unroll
    for (int j = 0; j < 12; ++j)
        cp16(sb + ES0_OFF + (j * THREADS + t) * 16, gB + j * THREADS + t);
    CP_COMMIT();

    // ---- half norms ----
#pragma unroll
    for (int i = 0; i < 8; ++i) hn[i * THREADS + t] = g_hn[i * THREADS + t];

    // ---- stage x tile: split fp32 -> [xh | xh | xl] fp16, stride KS ----
    const float4* xg = (const float4*)(x + (size_t)rowBase * D);
#pragma unroll
    for (int it = 0; it < 16; ++it) {
        int u = it * THREADS + t;
        int r = u >> 4, d = (u & 15) << 2;
        float4 v = xg[u];
        __half h0 = __float2half_rn(v.x), h1 = __float2half_rn(v.y);
        __half h2 = __float2half_rn(v.z), h3 = __float2half_rn(v.w);
        __half l0 = __float2half_rn(v.x - __half2float(h0));
        __half l1 = __float2half_rn(v.y - __half2float(h1));
        __half l2 = __float2half_rn(v.z - __half2float(h2));
        __half l3 = __float2half_rn(v.w - __half2float(h3));
        uint2 hv, lv;
        hv.x = pack2(h0, h1);
        hv.y = pack2(h2, h3);
        lv.x = pack2(l0, l1);
        lv.y = pack2(l2, l3);
        char* base = xs + r * (KS * 2) + d * 2;
        *(uint2*)(base)       = hv;
        *(uint2*)(base + 128) = hv;
        *(uint2*)(base + 256) = lv;
    }
    __syncthreads();

    // ---- preload A fragments: 12 ksteps x 2 mtiles (persistent) ----
    uint32_t afr[12][2][4];
#pragma unroll
    for (int mt = 0; mt < 2; ++mt) {
        const char* ab = xs + (w * 32 + mt * 16 + n4) * (KS * 2) + q * 4;
#pragma unroll
        for (int s = 0; s < 12; ++s) {
            afr[s][mt][0] = *(const uint32_t*)(ab + 32 * s);
            afr[s][mt][1] = *(const uint32_t*)(ab + 32 * s + 8 * (KS * 2));
            afr[s][mt][2] = *(const uint32_t*)(ab + 32 * s + 16);
            afr[s][mt][3] = *(const uint32_t*)(ab + 32 * s + 8 * (KS * 2) + 16);
        }
    }

    float bs[4];
    int   bi[4];
#pragma unroll
    for (int i = 0; i < 4; ++i) { bs[i] = -1e30f; bi[i] = 0; }

    for (int c = 0; c < NCHUNK; ++c) {
        CP_WAIT0();                       // chunk c landed (per-thread)
        __syncthreads();                  // visible to all; prev buf free

        if (c + 1 < NCHUNK) {             // prefetch c+1 into other buffer
            uint32_t dst = sb + (((c + 1) & 1) ? ES1_OFF : ES0_OFF);
            const uint4* gc = gB + (size_t)(c + 1) * CHUNK_U4;
#pragma unroll
            for (int j = 0; j < 12; ++j)
                cp16(dst + (j * THREADS + t) * 16, gc + j * THREADS + t);
            CP_COMMIT();
        }

        const char* esb = smem + ((c & 1) ? ES1_OFF : ES0_OFF);
        float acc[2][8][4];
#pragma unroll
        for (int mt = 0; mt < 2; ++mt)
#pragma unroll
            for (int nt = 0; nt < 8; ++nt)
#pragma unroll
                for (int i = 0; i < 4; ++i) acc[mt][nt][i] = 0.f;

#pragma unroll
        for (int s2 = 0; s2 < 6; ++s2) {
#pragma unroll
            for (int nt = 0; nt < 8; ++nt) {
                uint4 bv = *(const uint4*)(esb +
                    (((s2 * 8 + nt) * 32) + lane) * 16);
#pragma unroll
                for (int mt = 0; mt < 2; ++mt) {
                    mma16816(acc[mt][nt][0], acc[mt][nt][1],
                             acc[mt][nt][2], acc[mt][nt][3],
                             afr[2 * s2][mt][0], afr[2 * s2][mt][1],
                             afr[2 * s2][mt][2], afr[2 * s2][mt][3],
                             bv.x, bv.y);
                    mma16816(acc[mt][nt][0], acc[mt][nt][1],
                             acc[mt][nt][2], acc[mt][nt][3],
                             afr[2 * s2 + 1][mt][0], afr[2 * s2 + 1][mt][1],
                             afr[2 * s2 + 1][mt][2], afr[2 * s2 + 1][mt][3],
                             bv.z, bv.w);
                }
            }
        }

        // ---- epilogue: score = acc - hn, running argmax ----
#pragma unroll
        for (int mt = 0; mt < 2; ++mt) {
#pragma unroll
            for (int nt = 0; nt < 8; ++nt) {
                int cb = c * NCHK + nt * 8 + q * 2;
                float2 h = *(const float2*)&hn[cb];
                float s0 = acc[mt][nt][0] - h.x;
                float s1 = acc[mt][nt][1] - h.y;
                float s2v = acc[mt][nt][2] - h.x;
                float s3 = acc[mt][nt][3] - h.y;
                if (s0 > bs[mt * 2])     { bs[mt * 2] = s0;     bi[mt * 2] = cb; }
                if (s1 > bs[mt * 2])     { bs[mt * 2] = s1;     bi[mt * 2] = cb + 1; }
                if (s2v > bs[mt * 2 + 1]) { bs[mt * 2 + 1] = s2v; bi[mt * 2 + 1] = cb; }
                if (s3 > bs[mt * 2 + 1])  { bs[mt * 2 + 1] = s3;  bi[mt * 2 + 1] = cb + 1; }
            }
        }
    }

    // ---- reduce (score, idx) across the 4 lanes sharing each row ----
#pragma unroll
    for (int off = 1; off <= 2; off <<= 1) {
#pragma unroll
        for (int i = 0; i < 4; ++i) {
            float os = __shfl_xor_sync(0xffffffffu, bs[i], off);
            int   oi = __shfl_xor_sync(0xffffffffu, bi[i], off);
            if (os > bs[i] || (os == bs[i] && oi < bi[i])) {
                bs[i] = os; bi[i] = oi;
            }
        }
    }
    if (q == 0) {
#pragma unroll
        for (int mt = 0; mt < 2; ++mt) {
            bidx[w * 32 + mt * 16 + n4]     = bi[mt * 2];
            bidx[w * 32 + mt * 16 + n4 + 8] = bi[mt * 2 + 1];
        }
    }
    __syncthreads();

    // ---- gather quantized rows + partial MSE ----
    float lsum = 0.f;
    const float4* ebt4 = (const float4*)g_ebt;
    float4* of4 = (float4*)(out + (size_t)rowBase * D);
#pragma unroll
    for (int it = 0; it < 16; ++it) {
        int u = it * THREADS + t;          // float4 idx in [0, 2048)
        int r = u >> 4, d4 = u & 15;
        int b = bidx[r];
        float4 qv = ebt4[b * 16 + d4];
        float4 xv = xg[u];
        of4[u] = qv;
        float dx = qv.x - xv.x, dy = qv.y - xv.y;
        float dz = qv.z - xv.z, dw = qv.w - xv.w;
        lsum = fmaf(dx, dx, lsum);
        lsum = fmaf(dy, dy, lsum);
        lsum = fmaf(dz, dz, lsum);
        lsum = fmaf(dw, dw, lsum);
    }
#pragma unroll
    for (int o = 16; o; o >>= 1) lsum += __shfl_down_sync(0xffffffffu, lsum, o);
    if (lane == 0) wsum[w] = lsum;
    __syncthreads();

    // ---- last-CTA loss finalization (deterministic fixed-order sum) ----
    if (t == 0) {
        float s = wsum[0] + wsum[1] + wsum[2] + wsum[3];
        g_partials[blockIdx.x] = s;
        __threadfence();
        unsigned tk = atomicAdd(&g_ticket, 1u);
        flag[0] = (tk == gridDim.x - 1) ? 1 : 0;
    }
    __syncthreads();
    if (flag[0]) {
        const int ncta = gridDim.x;
        volatile const float* gp = g_partials;
        float s = 0.f;
        for (int i = t; i < ncta; i += THREADS) s += gp[i];
#pragma unroll
        for (int o = 16; o; o >>= 1)
            s += __shfl_down_sync(0xffffffffu, s, o);
        if (lane == 0) wsum[w] = s;
        __syncthreads();
        if (t == 0) {
            float tot = wsum[0] + wsum[1] + wsum[2] + wsum[3];
            out[out_idx] = 1.25f * tot * inv_total;
            g_ticket = 0;                  // reset for graph replay
        }
    }
}

// ---------------------------------------------------------------------------
extern "C" void kernel_launch(void* const* d_in, const int* in_sizes, int n_in,
                              void* d_out, int out_size) {
    const float* x   = (const float*)d_in[0];   // [N, 64]
    const float* emb = (const float*)d_in[1];   // [64, 1024]
    float* out = (float*)d_out;

    int nelem = in_sizes[0];
    int nrows = nelem / D;
    int ncta  = nrows / M_TILE;                 // 512

    cudaFuncSetAttribute(vq_main, cudaFuncAttributeMaxDynamicSharedMemorySize,
                         SM_TOTAL);

    vq_prep<<<160, 256>>>(emb);
    vq_main<<<ncta, THREADS, SM_TOTAL>>>(x, out, 1.0f / (float)nelem,
                                         out_size - 1);
}